// round 7
// baseline (speedup 1.0000x reference)
#include <cuda_runtime.h>
#include <cuda_bf16.h>

#define BB 256
#define TT 256
#define CP1 129
#define HH 128
#define G1 384
#define PRED_N (BB * (TT - 1) * 128)
#define PAR_N  (BB * TT * 2)

typedef unsigned long long ull;

// ---------------- scratch: __device__ globals -------------------------------
__device__ float g_gi1[(size_t)BB * TT * G1];   // (b,t,384) layer-1 input proj
__device__ float g_out1[(size_t)BB * TT * HH];  // (b,t,128) layer-1 outputs

// ---------------- helpers ----------------------------------------------------
__device__ __forceinline__ ull fma2(ull a, ull b, ull c) {
    ull d; asm("fma.rn.f32x2 %0,%1,%2,%3;" : "=l"(d) : "l"(a), "l"(b), "l"(c));
    return d;
}
__device__ __forceinline__ float2 unpack2(ull v) {
    float lo, hi; asm("mov.b64 {%0,%1},%2;" : "=f"(lo), "=f"(hi) : "l"(v));
    return make_float2(lo, hi);
}
__device__ __forceinline__ float sigf(float v) {
    return __fdividef(1.f, 1.f + __expf(-v));
}
__device__ __forceinline__ float tanh_(float v) {
    return __fdividef(2.f, 1.f + __expf(-2.f * v)) - 1.f;
}

// ---------------- K1: gi1 = x @ Wih1^T + bih1 -------------------------------
// Tile 64(t) x 128(n), microtile 4m x 8n (stride 16), f32x2 packed over K.
// grid (4 t-tiles, B, 3 n-tiles), block 256.
__global__ void __launch_bounds__(256, 2) k_gi1(
        const float* __restrict__ x, const int* __restrict__ lengths,
        const float* __restrict__ Wih1, const float* __restrict__ bih1) {
    int t0 = blockIdx.x * 64, b = blockIdx.y, n0 = blockIdx.z * 128;
    if (t0 >= lengths[b]) return;  // tile fully past length: never read

    __shared__ __align__(16) float sA[64][36];
    __shared__ __align__(16) float sW[128][36];
    ull acc[4][8];
#pragma unroll
    for (int i = 0; i < 4; i++)
#pragma unroll
        for (int j = 0; j < 8; j++) acc[i][j] = 0ull;

    const float* xb = x + (size_t)(b * TT + t0) * CP1;
    int tx = threadIdx.x & 15, ty = threadIdx.x >> 4;

    for (int kc = 0; kc < 128; kc += 32) {
        __syncthreads();
#pragma unroll
        for (int l = 0; l < 8; l++) {               // A: 64x32
            int idx = threadIdx.x + l * 256;
            int r = idx >> 5, c = idx & 31;
            sA[r][c] = xb[r * CP1 + kc + c];
        }
#pragma unroll
        for (int l = 0; l < 16; l++) {              // W: 128x32
            int idx = threadIdx.x + l * 256;
            int r = idx >> 5, c = idx & 31;
            sW[r][c] = Wih1[(size_t)(n0 + r) * CP1 + kc + c];
        }
        __syncthreads();
#pragma unroll
        for (int kq = 0; kq < 8; kq++) {
            ull a[4][2];
#pragma unroll
            for (int i = 0; i < 4; i++) {
                float4 v = *(const float4*)&sA[ty + 16 * i][kq * 4];
                a[i][0] = ((ull*)&v)[0]; a[i][1] = ((ull*)&v)[1];
            }
#pragma unroll
            for (int j = 0; j < 8; j++) {
                float4 v = *(const float4*)&sW[tx + 16 * j][kq * 4];
                ull w0 = ((ull*)&v)[0], w1 = ((ull*)&v)[1];
#pragma unroll
                for (int i = 0; i < 4; i++) {
                    acc[i][j] = fma2(a[i][0], w0, acc[i][j]);
                    acc[i][j] = fma2(a[i][1], w1, acc[i][j]);
                }
            }
        }
    }
    // epilogue: k=128 tail + bias + store
    float at[4], wt[8], bias[8];
#pragma unroll
    for (int i = 0; i < 4; i++) at[i] = xb[(ty + 16 * i) * CP1 + 128];
#pragma unroll
    for (int j = 0; j < 8; j++) {
        wt[j]   = Wih1[(size_t)(n0 + tx + 16 * j) * CP1 + 128];
        bias[j] = bih1[n0 + tx + 16 * j];
    }
#pragma unroll
    for (int i = 0; i < 4; i++) {
        int t = t0 + ty + 16 * i;
        float* orow = g_gi1 + (size_t)(b * TT + t) * G1 + n0;
#pragma unroll
        for (int j = 0; j < 8; j++) {
            float2 p = unpack2(acc[i][j]);
            orow[tx + 16 * j] = p.x + p.y + at[i] * wt[j] + bias[j];
        }
    }
}

// ---------------- K2: fused layer-1 recurrence + layer-2 GRU + params -------
// 128 CTAs; CTA p runs batch rows p and 255-p (lengths sorted desc => balanced).
// Thread g keeps Whh1 row g in 64 packed f32x2 registers.
// gi1 loads for step t+1 are issued at the TOP of step t (full-step slack to
// cover DRAM latency). Warps 0-5 compute Wih2 dots (one step behind); thread
// 383 runs the P=2 GRU-2 update and writes params.
__global__ void __launch_bounds__(384, 1)
k_recur1(const int* __restrict__ lengths, const float* __restrict__ h0_1,
         const float* __restrict__ Whh1, const float* __restrict__ bhh1,
         const float* __restrict__ h0_2, const float* __restrict__ Wih2,
         const float* __restrict__ Whh2, const float* __restrict__ bih2,
         const float* __restrict__ bhh2, float* __restrict__ out) {
    int g = threadIdx.x;
    int wid = g >> 5, lane = g & 31;
    ull W2[64];
    const ull* wr = (const ull*)(Whh1 + (size_t)g * HH);
#pragma unroll
    for (int i = 0; i < 64; i++) W2[i] = wr[i];
    float bh = bhh1[g];

    float4 wv2 = make_float4(0.f, 0.f, 0.f, 0.f);
    float bi2 = 0.f;
    if (wid < 6) { wv2 = ((const float4*)Wih2)[wid * 32 + lane]; bi2 = bih2[wid]; }

    __shared__ __align__(16) float s_h[HH];
    __shared__ float s_gh[G1];
    __shared__ float s_gi2[6];
    __shared__ float s_w2[18];   // Whh2 (12) + bhh2 (6)
    if (g < 12) s_w2[g] = Whh2[g];
    else if (g < 18) s_w2[g] = bhh2[g - 12];

#pragma unroll 1
    for (int rsel = 0; rsel < 2; rsel++) {
        int b = rsel ? (255 - (int)blockIdx.x) : (int)blockIdx.x;
        int len = lengths[b];
        if (g < HH) s_h[g] = h0_1[b * HH + g];
        float u0 = 0.f, u1 = 0.f;
        if (g == 383) { u0 = h0_2[b * 2]; u1 = h0_2[b * 2 + 1]; }
        __syncthreads();

        const float* gi = g_gi1 + (size_t)b * TT * G1;
        float* o1 = g_out1 + (size_t)b * TT * HH;
        float* par = out + PRED_N + (size_t)b * TT * 2;
        float pr = 0.f, pz = 0.f, pn = 0.f;
        if (g < HH) { pr = gi[g]; pz = gi[HH + g]; pn = gi[2 * HH + g]; }

#pragma unroll 1
        for (int t = 0; t < len; t++) {
            // -------- issue next step's gi1 loads FIRST (hide DRAM lat) -----
            float qr = 0.f, qz = 0.f, qn = 0.f;
            if (g < HH && t + 1 < len) {
                const float* gn = gi + (size_t)(t + 1) * G1;
                qr = __ldg(gn + g); qz = __ldg(gn + HH + g); qn = __ldg(gn + 2 * HH + g);
            }

            // -------- phase A: Whh1 matvec + (t>=1) Wih2 dots of s_h --------
            ull c0 = 0ull, c1 = 0ull, c2 = 0ull, c3 = 0ull;
            ull c4 = 0ull, c5 = 0ull, c6 = 0ull, c7 = 0ull;
            const ull* h2 = (const ull*)s_h;
#pragma unroll
            for (int i = 0; i < 64; i += 8) {
                c0 = fma2(W2[i],     h2[i],     c0);
                c1 = fma2(W2[i + 1], h2[i + 1], c1);
                c2 = fma2(W2[i + 2], h2[i + 2], c2);
                c3 = fma2(W2[i + 3], h2[i + 3], c3);
                c4 = fma2(W2[i + 4], h2[i + 4], c4);
                c5 = fma2(W2[i + 5], h2[i + 5], c5);
                c6 = fma2(W2[i + 6], h2[i + 6], c6);
                c7 = fma2(W2[i + 7], h2[i + 7], c7);
            }
            float2 f0 = unpack2(c0), f1 = unpack2(c1);
            float2 f2 = unpack2(c2), f3 = unpack2(c3);
            float2 f4 = unpack2(c4), f5 = unpack2(c5);
            float2 f6 = unpack2(c6), f7 = unpack2(c7);
            s_gh[g] = (((f0.x + f0.y) + (f1.x + f1.y)) +
                       ((f2.x + f2.y) + (f3.x + f3.y))) +
                      (((f4.x + f4.y) + (f5.x + f5.y)) +
                       ((f6.x + f6.y) + (f7.x + f7.y))) + bh;

            if (wid < 6 && t >= 1) {   // gi2 of out1[t-1] (== current s_h)
                float4 hv = *(const float4*)&s_h[lane * 4];
                float v = hv.x * wv2.x + hv.y * wv2.y + hv.z * wv2.z + hv.w * wv2.w;
                v += __shfl_xor_sync(0xFFFFFFFFu, v, 16);
                v += __shfl_xor_sync(0xFFFFFFFFu, v, 8);
                v += __shfl_xor_sync(0xFFFFFFFFu, v, 4);
                v += __shfl_xor_sync(0xFFFFFFFFu, v, 2);
                v += __shfl_xor_sync(0xFFFFFFFFu, v, 1);
                if (lane == 0) s_gi2[wid] = v + bi2;
            }
            __syncthreads();

            // -------- phase B: gate update | layer-2 scalar GRU -------------
            if (g < HH) {
                float r = sigf(pr + s_gh[g]);
                float z = sigf(pz + s_gh[HH + g]);
                float n = tanh_(pn + r * s_gh[2 * HH + g]);
                float hn = (1.f - z) * n + z * s_h[g];
                o1[(size_t)t * HH + g] = hn;
                s_h[g] = hn;
                pr = qr; pz = qz; pn = qn;
            } else if (g == 383 && t >= 1) {
                float hr0 = s_w2[0]  * u0 + s_w2[1]  * u1 + s_w2[12];
                float hr1 = s_w2[2]  * u0 + s_w2[3]  * u1 + s_w2[13];
                float hz0 = s_w2[4]  * u0 + s_w2[5]  * u1 + s_w2[14];
                float hz1 = s_w2[6]  * u0 + s_w2[7]  * u1 + s_w2[15];
                float hn0 = s_w2[8]  * u0 + s_w2[9]  * u1 + s_w2[16];
                float hn1 = s_w2[10] * u0 + s_w2[11] * u1 + s_w2[17];
                float r0 = sigf(s_gi2[0] + hr0), r1 = sigf(s_gi2[1] + hr1);
                float z0 = sigf(s_gi2[2] + hz0), z1 = sigf(s_gi2[3] + hz1);
                float n0 = tanh_(s_gi2[4] + r0 * hn0), n1 = tanh_(s_gi2[5] + r1 * hn1);
                u0 = (1.f - z0) * n0 + z0 * u0;
                u1 = (1.f - z1) * n1 + z1 * u1;
                par[(t - 1) * 2]     = __expf(-u0);
                par[(t - 1) * 2 + 1] = __expf(-u1);
            }
            __syncthreads();
        }

        // final layer-2 step (uses out1[len-1] == current s_h)
        if (wid < 6) {
            float4 hv = *(const float4*)&s_h[lane * 4];
            float v = hv.x * wv2.x + hv.y * wv2.y + hv.z * wv2.z + hv.w * wv2.w;
            v += __shfl_xor_sync(0xFFFFFFFFu, v, 16);
            v += __shfl_xor_sync(0xFFFFFFFFu, v, 8);
            v += __shfl_xor_sync(0xFFFFFFFFu, v, 4);
            v += __shfl_xor_sync(0xFFFFFFFFu, v, 2);
            v += __shfl_xor_sync(0xFFFFFFFFu, v, 1);
            if (lane == 0) s_gi2[wid] = v + bi2;
        }
        __syncthreads();
        if (g == 383) {
            float hr0 = s_w2[0]  * u0 + s_w2[1]  * u1 + s_w2[12];
            float hr1 = s_w2[2]  * u0 + s_w2[3]  * u1 + s_w2[13];
            float hz0 = s_w2[4]  * u0 + s_w2[5]  * u1 + s_w2[14];
            float hz1 = s_w2[6]  * u0 + s_w2[7]  * u1 + s_w2[15];
            float hn0 = s_w2[8]  * u0 + s_w2[9]  * u1 + s_w2[16];
            float hn1 = s_w2[10] * u0 + s_w2[11] * u1 + s_w2[17];
            float r0 = sigf(s_gi2[0] + hr0), r1 = sigf(s_gi2[1] + hr1);
            float z0 = sigf(s_gi2[2] + hz0), z1 = sigf(s_gi2[3] + hz1);
            float n0 = tanh_(s_gi2[4] + r0 * hn0), n1 = tanh_(s_gi2[5] + r1 * hn1);
            u0 = (1.f - z0) * n0 + z0 * u0;
            u1 = (1.f - z1) * n1 + z1 * u1;
            par[(len - 1) * 2]     = __expf(-u0);
            par[(len - 1) * 2 + 1] = __expf(-u1);
        }
        // padding params (exp(-0)=1) + lengths tail
        for (int tp = len + g; tp < TT; tp += 384) {
            par[tp * 2] = 1.f; par[tp * 2 + 1] = 1.f;
        }
        if (g == 0) out[PRED_N + PAR_N + b] = (float)len;
        __syncthreads();
    }
}

// ---------------- K3: FC head: preds = [out1, x_time] @ Wfc^T + bfc ---------
// Tile 64(t) x 128(n), microtile 4m x 8n. grid (4, B), block 256.
__global__ void __launch_bounds__(256, 2) k_fc(
        const float* __restrict__ x, const int* __restrict__ lengths,
        const float* __restrict__ Wfc, const float* __restrict__ bfc,
        float* __restrict__ out) {
    int t0 = blockIdx.x * 64, b = blockIdx.y;
    int len = lengths[b];
    float* ob = out + ((size_t)b * (TT - 1)) * 128;
    int rows = min(64, (TT - 1) - t0);

    if (t0 >= len - 1) {  // fully masked tile: zero-fill, skip GEMM
        for (int idx = threadIdx.x; idx < rows * 128; idx += 256) {
            int m = idx >> 7, n = idx & 127;
            ob[(size_t)(t0 + m) * 128 + n] = 0.f;
        }
        return;
    }

    __shared__ __align__(16) float sA[64][36];
    __shared__ __align__(16) float sW[128][36];
    ull acc[4][8];
#pragma unroll
    for (int i = 0; i < 4; i++)
#pragma unroll
        for (int j = 0; j < 8; j++) acc[i][j] = 0ull;

    const float* ab = g_out1 + (size_t)(b * TT + t0) * HH;
    int tx = threadIdx.x & 15, ty = threadIdx.x >> 4;

    for (int kc = 0; kc < 128; kc += 32) {
        __syncthreads();
#pragma unroll
        for (int l = 0; l < 8; l++) {               // A: out1 rows (stride 128)
            int idx = threadIdx.x + l * 256;
            int r = idx >> 5, c = idx & 31;
            sA[r][c] = ab[r * HH + kc + c];
        }
#pragma unroll
        for (int l = 0; l < 16; l++) {              // W: Wfc rows (stride 129)
            int idx = threadIdx.x + l * 256;
            int r = idx >> 5, c = idx & 31;
            sW[r][c] = Wfc[(size_t)r * CP1 + kc + c];
        }
        __syncthreads();
#pragma unroll
        for (int kq = 0; kq < 8; kq++) {
            ull a[4][2];
#pragma unroll
            for (int i = 0; i < 4; i++) {
                float4 v = *(const float4*)&sA[ty + 16 * i][kq * 4];
                a[i][0] = ((ull*)&v)[0]; a[i][1] = ((ull*)&v)[1];
            }
#pragma unroll
            for (int j = 0; j < 8; j++) {
                float4 v = *(const float4*)&sW[tx + 16 * j][kq * 4];
                ull w0 = ((ull*)&v)[0], w1 = ((ull*)&v)[1];
#pragma unroll
                for (int i = 0; i < 4; i++) {
                    acc[i][j] = fma2(a[i][0], w0, acc[i][j]);
                    acc[i][j] = fma2(a[i][1], w1, acc[i][j]);
                }
            }
        }
    }
    // epilogue: k=128 tail = time feature; mask; store
    float at[4], wt[8], bias[8];
#pragma unroll
    for (int i = 0; i < 4; i++) {
        int t = t0 + ty + 16 * i;   // <= 255: in-bounds for x
        at[i] = x[(size_t)(b * TT + t) * CP1];
    }
#pragma unroll
    for (int j = 0; j < 8; j++) {
        wt[j]   = Wfc[(size_t)(tx + 16 * j) * CP1 + 128];
        bias[j] = bfc[tx + 16 * j];
    }
#pragma unroll
    for (int i = 0; i < 4; i++) {
        int t = t0 + ty + 16 * i;
        if (t >= TT - 1) continue;
        float* orow = ob + (size_t)t * 128;
        bool valid = (t < len - 1);
#pragma unroll
        for (int j = 0; j < 8; j++) {
            float2 p = unpack2(acc[i][j]);
            float v = p.x + p.y + at[i] * wt[j] + bias[j];
            orow[tx + 16 * j] = valid ? v : 0.f;
        }
    }
}

// ---------------- launch -----------------------------------------------------
extern "C" void kernel_launch(void* const* d_in, const int* in_sizes, int n_in,
                              void* d_out, int out_size) {
    const float* x      = (const float*)d_in[0];
    const int*   lens   = (const int*)  d_in[1];
    const float* h0_1   = (const float*)d_in[2];
    const float* h0_2   = (const float*)d_in[3];
    const float* Wih1   = (const float*)d_in[4];
    const float* Whh1   = (const float*)d_in[5];
    const float* bih1   = (const float*)d_in[6];
    const float* bhh1   = (const float*)d_in[7];
    const float* Wih2   = (const float*)d_in[8];
    const float* Whh2   = (const float*)d_in[9];
    const float* bih2   = (const float*)d_in[10];
    const float* bhh2   = (const float*)d_in[11];
    const float* Wfc    = (const float*)d_in[12];
    const float* bfc    = (const float*)d_in[13];
    float* out = (float*)d_out;

    k_gi1  <<<dim3(4, BB, 3), 256>>>(x, lens, Wih1, bih1);
    k_recur1<<<128, 384>>>(lens, h0_1, Whh1, bhh1, h0_2, Wih2, Whh2, bih2, bhh2, out);
    k_fc   <<<dim3(4, BB), 256>>>(x, lens, Wfc, bfc, out);
}

// round 8
// speedup vs baseline: 1.0935x; 1.0935x over previous
#include <cuda_runtime.h>
#include <cuda_bf16.h>

#define BB 256
#define TT 256
#define CP1 129
#define HH 128
#define G1 384
#define PRED_N (BB * (TT - 1) * 128)
#define PAR_N  (BB * TT * 2)

typedef unsigned long long ull;

// ---------------- scratch: __device__ globals -------------------------------
__device__ float g_gi1[(size_t)BB * TT * G1];   // (b,t,384) layer-1 input proj
__device__ float g_out1[(size_t)BB * TT * HH];  // (b,t,128) layer-1 outputs

// ---------------- helpers ----------------------------------------------------
__device__ __forceinline__ ull fma2(ull a, ull b, ull c) {
    ull d; asm("fma.rn.f32x2 %0,%1,%2,%3;" : "=l"(d) : "l"(a), "l"(b), "l"(c));
    return d;
}
__device__ __forceinline__ float2 unpack2(ull v) {
    float lo, hi; asm("mov.b64 {%0,%1},%2;" : "=f"(lo), "=f"(hi) : "l"(v));
    return make_float2(lo, hi);
}
__device__ __forceinline__ float sigf(float v) {
    return __fdividef(1.f, 1.f + __expf(-v));
}
__device__ __forceinline__ float tanh_(float v) {
    return __fdividef(2.f, 1.f + __expf(-2.f * v)) - 1.f;
}

// ---------------- K1: gi1 = x @ Wih1^T + bih1 -------------------------------
// Tile 64(t) x 64(n), microtile 4m x 4n (strided 16), f32x2 packed over K.
// grid (4 t-tiles, B, 6 n-tiles), block 256, 3 CTAs/SM (occupancy experiment).
__global__ void __launch_bounds__(256, 3) k_gi1(
        const float* __restrict__ x, const int* __restrict__ lengths,
        const float* __restrict__ Wih1, const float* __restrict__ bih1) {
    int t0 = blockIdx.x * 64, b = blockIdx.y, n0 = blockIdx.z * 64;
    if (t0 >= lengths[b]) return;  // tile fully past length: never read

    __shared__ __align__(16) float sA[64][36];
    __shared__ __align__(16) float sW[64][36];
    ull acc[4][4];
#pragma unroll
    for (int i = 0; i < 4; i++)
#pragma unroll
        for (int j = 0; j < 4; j++) acc[i][j] = 0ull;

    const float* xb = x + (size_t)(b * TT + t0) * CP1;
    int tx = threadIdx.x & 15, ty = threadIdx.x >> 4;

    for (int kc = 0; kc < 128; kc += 32) {
        __syncthreads();
#pragma unroll
        for (int l = 0; l < 8; l++) {
            int idx = threadIdx.x + l * 256;
            int r = idx >> 5, c = idx & 31;
            sA[r][c] = xb[r * CP1 + kc + c];
            sW[r][c] = Wih1[(size_t)(n0 + r) * CP1 + kc + c];
        }
        __syncthreads();
#pragma unroll
        for (int kq = 0; kq < 8; kq++) {
            ull w[4][2], a[4][2];
#pragma unroll
            for (int j = 0; j < 4; j++) {
                float4 v = *(const float4*)&sW[tx + 16 * j][kq * 4];
                w[j][0] = ((ull*)&v)[0]; w[j][1] = ((ull*)&v)[1];
            }
#pragma unroll
            for (int i = 0; i < 4; i++) {
                float4 v = *(const float4*)&sA[ty + 16 * i][kq * 4];
                a[i][0] = ((ull*)&v)[0]; a[i][1] = ((ull*)&v)[1];
            }
#pragma unroll
            for (int i = 0; i < 4; i++)
#pragma unroll
                for (int j = 0; j < 4; j++) {
                    acc[i][j] = fma2(a[i][0], w[j][0], acc[i][j]);
                    acc[i][j] = fma2(a[i][1], w[j][1], acc[i][j]);
                }
        }
    }
    // epilogue: k=128 tail + bias + store
    float at[4], wt[4], bias[4];
#pragma unroll
    for (int i = 0; i < 4; i++) at[i] = xb[(ty + 16 * i) * CP1 + 128];
#pragma unroll
    for (int j = 0; j < 4; j++) {
        wt[j]   = Wih1[(size_t)(n0 + tx + 16 * j) * CP1 + 128];
        bias[j] = bih1[n0 + tx + 16 * j];
    }
#pragma unroll
    for (int i = 0; i < 4; i++) {
        int t = t0 + ty + 16 * i;
        float* orow = g_gi1 + (size_t)(b * TT + t) * G1 + n0;
#pragma unroll
        for (int j = 0; j < 4; j++) {
            float2 p = unpack2(acc[i][j]);
            orow[tx + 16 * j] = p.x + p.y + at[i] * wt[j] + bias[j];
        }
    }
}

// ---------------- K2: fused layer-1 recurrence + layer-2 GRU + params -------
// 128 CTAs; CTA p runs batch rows p and 255-p (lengths sorted desc => balanced).
// Thread g keeps Whh1 row g in 64 packed f32x2 registers.
// Warps 0-5 additionally compute the 6 Wih2 dot products of s_h (pipelined
// one step behind); thread 383 runs the P=2 GRU-2 update and writes params.
__global__ void __launch_bounds__(384, 1)
k_recur1(const int* __restrict__ lengths, const float* __restrict__ h0_1,
         const float* __restrict__ Whh1, const float* __restrict__ bhh1,
         const float* __restrict__ h0_2, const float* __restrict__ Wih2,
         const float* __restrict__ Whh2, const float* __restrict__ bih2,
         const float* __restrict__ bhh2, float* __restrict__ out) {
    int g = threadIdx.x;
    int wid = g >> 5, lane = g & 31;
    ull W2[64];
    const ull* wr = (const ull*)(Whh1 + (size_t)g * HH);
#pragma unroll
    for (int i = 0; i < 64; i++) W2[i] = wr[i];
    float bh = bhh1[g];

    float4 wv2 = make_float4(0.f, 0.f, 0.f, 0.f);
    float bi2 = 0.f;
    if (wid < 6) { wv2 = ((const float4*)Wih2)[wid * 32 + lane]; bi2 = bih2[wid]; }

    __shared__ __align__(16) float s_h[HH];
    __shared__ float s_gh[G1];
    __shared__ float s_gi2[6];
    __shared__ float s_w2[18];   // Whh2 (12) + bhh2 (6)
    if (g < 12) s_w2[g] = Whh2[g];
    else if (g < 18) s_w2[g] = bhh2[g - 12];

#pragma unroll 1
    for (int rsel = 0; rsel < 2; rsel++) {
        int b = rsel ? (255 - (int)blockIdx.x) : (int)blockIdx.x;
        int len = lengths[b];
        if (g < HH) s_h[g] = h0_1[b * HH + g];
        float u0 = 0.f, u1 = 0.f;
        if (g == 383) { u0 = h0_2[b * 2]; u1 = h0_2[b * 2 + 1]; }
        __syncthreads();

        const float* gi = g_gi1 + (size_t)b * TT * G1;
        float* o1 = g_out1 + (size_t)b * TT * HH;
        float* par = out + PRED_N + (size_t)b * TT * 2;
        float pr = 0.f, pz = 0.f, pn = 0.f;
        if (g < HH) { pr = gi[g]; pz = gi[HH + g]; pn = gi[2 * HH + g]; }

#pragma unroll 1
        for (int t = 0; t < len; t++) {
            // -------- phase A: Whh1 matvec + (t>=1) Wih2 dots of s_h --------
            ull a0 = 0ull, a1 = 0ull, a2 = 0ull, a3 = 0ull;
            const ull* h2 = (const ull*)s_h;
#pragma unroll
            for (int i = 0; i < 64; i += 4) {
                a0 = fma2(W2[i],     h2[i],     a0);
                a1 = fma2(W2[i + 1], h2[i + 1], a1);
                a2 = fma2(W2[i + 2], h2[i + 2], a2);
                a3 = fma2(W2[i + 3], h2[i + 3], a3);
            }
            float2 f0 = unpack2(a0), f1 = unpack2(a1);
            float2 f2 = unpack2(a2), f3 = unpack2(a3);
            s_gh[g] = ((f0.x + f0.y) + (f1.x + f1.y)) +
                      ((f2.x + f2.y) + (f3.x + f3.y)) + bh;

            if (wid < 6 && t >= 1) {   // gi2 of out1[t-1] (== current s_h)
                float4 hv = *(const float4*)&s_h[lane * 4];
                float v = hv.x * wv2.x + hv.y * wv2.y + hv.z * wv2.z + hv.w * wv2.w;
                v += __shfl_xor_sync(0xFFFFFFFFu, v, 16);
                v += __shfl_xor_sync(0xFFFFFFFFu, v, 8);
                v += __shfl_xor_sync(0xFFFFFFFFu, v, 4);
                v += __shfl_xor_sync(0xFFFFFFFFu, v, 2);
                v += __shfl_xor_sync(0xFFFFFFFFu, v, 1);
                if (lane == 0) s_gi2[wid] = v + bi2;
            }
            __syncthreads();

            // -------- phase B: gate update | layer-2 scalar GRU -------------
            if (g < HH) {
                float r = sigf(pr + s_gh[g]);
                float z = sigf(pz + s_gh[HH + g]);
                float n = tanh_(pn + r * s_gh[2 * HH + g]);
                float hn = (1.f - z) * n + z * s_h[g];
                o1[(size_t)t * HH + g] = hn;
                if (t + 1 < len) {
                    const float* gn = gi + (size_t)(t + 1) * G1;
                    pr = gn[g]; pz = gn[HH + g]; pn = gn[2 * HH + g];
                }
                s_h[g] = hn;
            } else if (g == 383 && t >= 1) {
                float hr0 = s_w2[0]  * u0 + s_w2[1]  * u1 + s_w2[12];
                float hr1 = s_w2[2]  * u0 + s_w2[3]  * u1 + s_w2[13];
                float hz0 = s_w2[4]  * u0 + s_w2[5]  * u1 + s_w2[14];
                float hz1 = s_w2[6]  * u0 + s_w2[7]  * u1 + s_w2[15];
                float hn0 = s_w2[8]  * u0 + s_w2[9]  * u1 + s_w2[16];
                float hn1 = s_w2[10] * u0 + s_w2[11] * u1 + s_w2[17];
                float r0 = sigf(s_gi2[0] + hr0), r1 = sigf(s_gi2[1] + hr1);
                float z0 = sigf(s_gi2[2] + hz0), z1 = sigf(s_gi2[3] + hz1);
                float n0 = tanh_(s_gi2[4] + r0 * hn0), n1 = tanh_(s_gi2[5] + r1 * hn1);
                u0 = (1.f - z0) * n0 + z0 * u0;
                u1 = (1.f - z1) * n1 + z1 * u1;
                par[(t - 1) * 2]     = __expf(-u0);
                par[(t - 1) * 2 + 1] = __expf(-u1);
            }
            __syncthreads();
        }

        // final layer-2 step (uses out1[len-1] == current s_h)
        if (wid < 6) {
            float4 hv = *(const float4*)&s_h[lane * 4];
            float v = hv.x * wv2.x + hv.y * wv2.y + hv.z * wv2.z + hv.w * wv2.w;
            v += __shfl_xor_sync(0xFFFFFFFFu, v, 16);
            v += __shfl_xor_sync(0xFFFFFFFFu, v, 8);
            v += __shfl_xor_sync(0xFFFFFFFFu, v, 4);
            v += __shfl_xor_sync(0xFFFFFFFFu, v, 2);
            v += __shfl_xor_sync(0xFFFFFFFFu, v, 1);
            if (lane == 0) s_gi2[wid] = v + bi2;
        }
        __syncthreads();
        if (g == 383) {
            float hr0 = s_w2[0]  * u0 + s_w2[1]  * u1 + s_w2[12];
            float hr1 = s_w2[2]  * u0 + s_w2[3]  * u1 + s_w2[13];
            float hz0 = s_w2[4]  * u0 + s_w2[5]  * u1 + s_w2[14];
            float hz1 = s_w2[6]  * u0 + s_w2[7]  * u1 + s_w2[15];
            float hn0 = s_w2[8]  * u0 + s_w2[9]  * u1 + s_w2[16];
            float hn1 = s_w2[10] * u0 + s_w2[11] * u1 + s_w2[17];
            float r0 = sigf(s_gi2[0] + hr0), r1 = sigf(s_gi2[1] + hr1);
            float z0 = sigf(s_gi2[2] + hz0), z1 = sigf(s_gi2[3] + hz1);
            float n0 = tanh_(s_gi2[4] + r0 * hn0), n1 = tanh_(s_gi2[5] + r1 * hn1);
            u0 = (1.f - z0) * n0 + z0 * u0;
            u1 = (1.f - z1) * n1 + z1 * u1;
            par[(len - 1) * 2]     = __expf(-u0);
            par[(len - 1) * 2 + 1] = __expf(-u1);
        }
        // padding params (exp(-0)=1) + lengths tail
        for (int tp = len + g; tp < TT; tp += 384) {
            par[tp * 2] = 1.f; par[tp * 2 + 1] = 1.f;
        }
        if (g == 0) out[PRED_N + PAR_N + b] = (float)len;
        __syncthreads();
    }
}

// ---------------- K3: FC head: preds = [out1, x_time] @ Wfc^T + bfc ---------
// Same 64x64 f32x2 microkernel, 3 CTAs/SM. grid (4, B, 2), block 256.
__global__ void __launch_bounds__(256, 3) k_fc(
        const float* __restrict__ x, const int* __restrict__ lengths,
        const float* __restrict__ Wfc, const float* __restrict__ bfc,
        float* __restrict__ out) {
    int t0 = blockIdx.x * 64, b = blockIdx.y, n0 = blockIdx.z * 64;
    int len = lengths[b];
    float* ob = out + ((size_t)b * (TT - 1)) * 128;
    int rows = min(64, (TT - 1) - t0);

    if (t0 >= len - 1) {  // fully masked tile: zero-fill, skip GEMM
        for (int idx = threadIdx.x; idx < rows * 64; idx += 256) {
            int m = idx >> 6, n = idx & 63;
            ob[(size_t)(t0 + m) * 128 + n0 + n] = 0.f;
        }
        return;
    }

    __shared__ __align__(16) float sA[64][36];
    __shared__ __align__(16) float sW[64][36];
    ull acc[4][4];
#pragma unroll
    for (int i = 0; i < 4; i++)
#pragma unroll
        for (int j = 0; j < 4; j++) acc[i][j] = 0ull;

    const float* ab = g_out1 + (size_t)(b * TT + t0) * HH;
    int tx = threadIdx.x & 15, ty = threadIdx.x >> 4;

    for (int kc = 0; kc < 128; kc += 32) {
        __syncthreads();
#pragma unroll
        for (int l = 0; l < 8; l++) {
            int idx = threadIdx.x + l * 256;
            int r = idx >> 5, c = idx & 31;
            sA[r][c] = ab[r * HH + kc + c];
            sW[r][c] = Wfc[(size_t)(n0 + r) * CP1 + kc + c];
        }
        __syncthreads();
#pragma unroll
        for (int kq = 0; kq < 8; kq++) {
            ull w[4][2], a[4][2];
#pragma unroll
            for (int j = 0; j < 4; j++) {
                float4 v = *(const float4*)&sW[tx + 16 * j][kq * 4];
                w[j][0] = ((ull*)&v)[0]; w[j][1] = ((ull*)&v)[1];
            }
#pragma unroll
            for (int i = 0; i < 4; i++) {
                float4 v = *(const float4*)&sA[ty + 16 * i][kq * 4];
                a[i][0] = ((ull*)&v)[0]; a[i][1] = ((ull*)&v)[1];
            }
#pragma unroll
            for (int i = 0; i < 4; i++)
#pragma unroll
                for (int j = 0; j < 4; j++) {
                    acc[i][j] = fma2(a[i][0], w[j][0], acc[i][j]);
                    acc[i][j] = fma2(a[i][1], w[j][1], acc[i][j]);
                }
        }
    }
    // epilogue: k=128 tail = time feature; mask; store
    float at[4], wt[4], bias[4];
#pragma unroll
    for (int i = 0; i < 4; i++) {
        int t = t0 + ty + 16 * i;   // <= 255: in-bounds for x
        at[i] = x[(size_t)(b * TT + t) * CP1];
    }
#pragma unroll
    for (int j = 0; j < 4; j++) {
        wt[j]   = Wfc[(size_t)(n0 + tx + 16 * j) * CP1 + 128];
        bias[j] = bfc[n0 + tx + 16 * j];
    }
#pragma unroll
    for (int i = 0; i < 4; i++) {
        int t = t0 + ty + 16 * i;
        if (t >= TT - 1) continue;
        float* orow = ob + (size_t)t * 128 + n0;
        bool valid = (t < len - 1);
#pragma unroll
        for (int j = 0; j < 4; j++) {
            float2 p = unpack2(acc[i][j]);
            float v = p.x + p.y + at[i] * wt[j] + bias[j];
            orow[tx + 16 * j] = valid ? v : 0.f;
        }
    }
}

// ---------------- launch -----------------------------------------------------
extern "C" void kernel_launch(void* const* d_in, const int* in_sizes, int n_in,
                              void* d_out, int out_size) {
    const float* x      = (const float*)d_in[0];
    const int*   lens   = (const int*)  d_in[1];
    const float* h0_1   = (const float*)d_in[2];
    const float* h0_2   = (const float*)d_in[3];
    const float* Wih1   = (const float*)d_in[4];
    const float* Whh1   = (const float*)d_in[5];
    const float* bih1   = (const float*)d_in[6];
    const float* bhh1   = (const float*)d_in[7];
    const float* Wih2   = (const float*)d_in[8];
    const float* Whh2   = (const float*)d_in[9];
    const float* bih2   = (const float*)d_in[10];
    const float* bhh2   = (const float*)d_in[11];
    const float* Wfc    = (const float*)d_in[12];
    const float* bfc    = (const float*)d_in[13];
    float* out = (float*)d_out;

    k_gi1  <<<dim3(4, BB, 6), 256>>>(x, lens, Wih1, bih1);
    k_recur1<<<128, 384>>>(lens, h0_1, Whh1, bhh1, h0_2, Wih2, Whh2, bih2, bhh2, out);
    k_fc   <<<dim3(4, BB, 2), 256>>>(x, lens, Wfc, bfc, out);
}